// round 15
// baseline (speedup 1.0000x reference)
#include <cuda_runtime.h>
#include <cuda_fp16.h>
#include <cstdint>

#define BATCH 32
#define NN    1024
#define DD    128
#define LL    2
#define MTOT  (BATCH * NN)
#define BN_EPS 1e-5f
#define BN_BLOCKS 256

// ---------------- scratch ----------------
__device__ __half g_adjH[(size_t)BATCH * NN * NN];
__device__ __half g_hHi[MTOT * DD];
__device__ __half g_pHi[MTOT * DD];
__device__ __half g_pLo[MTOT * DD];
__device__ __half g_W1Hi[LL * DD * DD];
__device__ __half g_W1Lo[LL * DD * DD];
__device__ __half g_W2Hi[LL * DD * DD];
__device__ __half g_W2Lo[LL * DD * DD];
__device__ float g_z[MTOT * DD];
__device__ float g_partS1[BN_BLOCKS * DD];
__device__ float g_partQ1[BN_BLOCKS * DD];
__device__ float g_partS2[BN_BLOCKS * DD];
__device__ float g_partQ2[BN_BLOCKS * DD];

// ---------------- helpers ----------------
__device__ __forceinline__ uint32_t smem_u32(const void* p) {
    uint32_t a;
    asm("{ .reg .u64 t; cvta.to.shared.u64 t, %1; cvt.u32.u64 %0, t; }" : "=r"(a) : "l"(p));
    return a;
}
__device__ __forceinline__ void ldsm_x4(uint32_t* r, uint32_t addr) {
    asm volatile("ldmatrix.sync.aligned.m8n8.x4.shared.b16 {%0,%1,%2,%3}, [%4];"
                 : "=r"(r[0]), "=r"(r[1]), "=r"(r[2]), "=r"(r[3]) : "r"(addr));
}
__device__ __forceinline__ void ldsm_x4_t(uint32_t* r, uint32_t addr) {
    asm volatile("ldmatrix.sync.aligned.m8n8.x4.trans.shared.b16 {%0,%1,%2,%3}, [%4];"
                 : "=r"(r[0]), "=r"(r[1]), "=r"(r[2]), "=r"(r[3]) : "r"(addr));
}
__device__ __forceinline__ void mma_fp16(float* c, const uint32_t* a, const uint32_t* b) {
    asm volatile(
        "mma.sync.aligned.m16n8k16.row.col.f32.f16.f16.f32 "
        "{%0,%1,%2,%3}, {%4,%5,%6,%7}, {%8,%9}, {%0,%1,%2,%3};"
        : "+f"(c[0]), "+f"(c[1]), "+f"(c[2]), "+f"(c[3])
        : "r"(a[0]), "r"(a[1]), "r"(a[2]), "r"(a[3]), "r"(b[0]), "r"(b[1]));
}
__device__ __forceinline__ void cp_async16(uint32_t dst, const void* src) {
    asm volatile("cp.async.cg.shared.global [%0], [%1], 16;" :: "r"(dst), "l"(src));
}
#define CP_COMMIT() asm volatile("cp.async.commit_group;" ::: "memory")
#define CP_WAIT1()  asm volatile("cp.async.wait_group 1;"  ::: "memory")
#define CP_WAIT0()  asm volatile("cp.async.wait_group 0;"  ::: "memory")

__device__ __forceinline__ uint32_t pack_f16(float x, float y) {
    __half2 t = __floats2half2_rn(x, y);
    return *reinterpret_cast<uint32_t*>(&t);
}

// =================================================================
// Pool layer-1 GEMM (fp16, 1 term), 2 CTAs/SM. Convert-at-load: no
// register staging across the MMA phase.
// =================================================================
#define AH_BUF   18432
#define PB_OFF   36864
#define PB_STG   17408
#define POOL_SMEM 89088

__global__ __launch_bounds__(512, 2)
void gemm_pool_convert(const float* __restrict__ A,
                       const __half* __restrict__ Bhi,
                       __half* __restrict__ adjHOut,
                       __half* __restrict__ outHi,
                       __half* __restrict__ outLo) {
    constexpr int NC = NN / 64;

    const size_t aOff = (size_t)blockIdx.y * NN * NN + (size_t)blockIdx.x * 128 * NN;
    const size_t bOff = (size_t)blockIdx.y * NN * DD;
    const size_t oOff = (size_t)blockIdx.y * NN * DD + (size_t)blockIdx.x * 128 * DD;
    A += aOff;
    adjHOut += aOff;
    Bhi += bOff;

    extern __shared__ char smem[];
    const uint32_t sbase = smem_u32(smem);

    const int tid  = threadIdx.x;
    const int lane = tid & 31;
    const int wid  = tid >> 5;
    const int wm   = wid & 3;
    const int wn   = wid >> 2;
    const int sub  = lane >> 3;
    const int r8   = lane & 7;

    const uint32_t rowA  = wm * 32 + (sub & 1) * 8 + r8;
    const uint32_t colA  = (sub >> 1) * 8;
    const uint32_t rowB8 = (sub & 1) * 8 + r8;
    const uint32_t colB  = wn * 32 + (sub >> 1) * 8;

    const int aRow[4] = { (tid) >> 4, (tid + 512) >> 4, (tid + 1024) >> 4, (tid + 1536) >> 4 };
    const int aSeg = tid & 15;

    float acc[2][4][4];
#pragma unroll
    for (int i = 0; i < 2; i++)
#pragma unroll
        for (int j = 0; j < 4; j++)
#pragma unroll
            for (int k = 0; k < 4; k++) acc[i][j][k] = 0.f;

    auto issueB = [&](int c) {
        const uint32_t sb = sbase + PB_OFF + (uint32_t)(c % 3) * PB_STG;
#pragma unroll
        for (int p = 0; p < 2; p++) {
            int i = tid + p * 512;
            int row = i >> 4, ch = i & 15;
            cp_async16(sb + row * 272 + ch * 16, Bhi + (size_t)(c * 64 + row) * DD + ch * 8);
        }
    };
    // Load chunk c, convert to fp16 immediately, STS buf(c&1) + STG adjH.
    auto loadCvtStore = [&](int c) {
        char* dhi = smem + (c & 1) * AH_BUF;
        float4 v[4];
#pragma unroll
        for (int p = 0; p < 4; p++)
            v[p] = *reinterpret_cast<const float4*>(A + (size_t)aRow[p] * NN + c * 64 + aSeg * 4);
#pragma unroll
        for (int p = 0; p < 4; p++) {
            uint2 hv;
            hv.x = pack_f16(v[p].x, v[p].y);
            hv.y = pack_f16(v[p].z, v[p].w);
            *reinterpret_cast<uint2*>(dhi + aRow[p] * 144 + aSeg * 8) = hv;
            *reinterpret_cast<uint2*>(adjHOut + (size_t)aRow[p] * NN + c * 64 + aSeg * 4) = hv;
        }
    };

    loadCvtStore(0);
    issueB(0); CP_COMMIT();
    issueB(1); CP_COMMIT();
    CP_WAIT1();
    __syncthreads();

    for (int c = 0; c < NC; c++) {
        if (c + 1 < NC) loadCvtStore(c + 1);
        if (c + 2 < NC) issueB(c + 2);
        CP_COMMIT();

        const uint32_t stA = sbase + (uint32_t)(c & 1) * AH_BUF;
        const uint32_t stB = sbase + PB_OFF + (uint32_t)(c % 3) * PB_STG;
#pragma unroll
        for (int ks = 0; ks < 4; ks++) {
            uint32_t ah[2][4], bh[2][4];
#pragma unroll
            for (int mb = 0; mb < 2; mb++) {
                uint32_t ad = stA + (rowA + mb * 16) * 144 + (ks * 16 + colA) * 2;
                ldsm_x4(ah[mb], ad);
            }
#pragma unroll
            for (int g = 0; g < 2; g++) {
                uint32_t bd = stB + (ks * 16 + rowB8) * 272 + (colB + g * 16) * 2;
                ldsm_x4_t(bh[g], bd);
            }
#pragma unroll
            for (int mb = 0; mb < 2; mb++)
#pragma unroll
                for (int nb = 0; nb < 4; nb++)
                    mma_fp16(acc[mb][nb], ah[mb], &bh[nb >> 1][(nb & 1) * 2]);
        }

        CP_WAIT1();
        __syncthreads();
    }

    const int er = lane >> 2;
    const int ec = (lane & 3) * 2;
#pragma unroll
    for (int mb = 0; mb < 2; mb++)
#pragma unroll
        for (int nb = 0; nb < 4; nb++) {
            int row = wm * 32 + mb * 16 + er;
            int col = wn * 32 + nb * 8 + ec;
            float2 v0 = make_float2(acc[mb][nb][0], acc[mb][nb][1]);
            float2 v1 = make_float2(acc[mb][nb][2], acc[mb][nb][3]);
            __half h0 = __float2half_rn(v0.x), h1 = __float2half_rn(v0.y);
            __half h2 = __float2half_rn(v1.x), h3 = __float2half_rn(v1.y);
            uint32_t hi0 = pack_f16(v0.x, v0.y);
            uint32_t hi1 = pack_f16(v1.x, v1.y);
            uint32_t lo0 = pack_f16(v0.x - __half2float(h0), v0.y - __half2float(h1));
            uint32_t lo1 = pack_f16(v1.x - __half2float(h2), v1.y - __half2float(h3));
            *reinterpret_cast<uint32_t*>(outHi + oOff + (size_t)row * DD + col) = hi0;
            *reinterpret_cast<uint32_t*>(outLo + oOff + (size_t)row * DD + col) = lo0;
            *reinterpret_cast<uint32_t*>(outHi + oOff + (size_t)(row + 8) * DD + col) = hi1;
            *reinterpret_cast<uint32_t*>(outLo + oOff + (size_t)(row + 8) * DD + col) = lo1;
        }
}

// =================================================================
// Unified fp16 GEMM (unchanged).
// =================================================================
template <int KA, int NTERMS, bool BIASED, int MINB>
__global__ __launch_bounds__(512, MINB)
void gemm_f16(const __half* __restrict__ Ahi, const __half* __restrict__ Alo,
              const __half* __restrict__ Bhi, const __half* __restrict__ Blo,
              const float* __restrict__ bias,
              float* __restrict__ outF,
              __half* __restrict__ outHi, __half* __restrict__ outLo,
              float* __restrict__ pS, float* __restrict__ pQ) {
    constexpr int NC  = KA / 64;
    constexpr int NH  = (NTERMS == 3) ? 2 : 1;
    constexpr int A_SEC = 128 * 144;
    constexpr int B_SEC = 64 * 272;
    constexpr int OFF_B = NH * A_SEC;
    constexpr int STAGE = OFF_B + NH * B_SEC;
    constexpr int SBUF_OFF = 3 * STAGE;

    size_t aOff, bOff, oOff;
    if (KA == NN) {
        aOff = (size_t)blockIdx.y * NN * NN + (size_t)blockIdx.x * 128 * NN;
        bOff = (size_t)blockIdx.y * NN * DD;
        oOff = (size_t)blockIdx.y * NN * DD + (size_t)blockIdx.x * 128 * DD;
    } else {
        aOff = (size_t)blockIdx.x * 128 * DD;
        bOff = 0;
        oOff = (size_t)blockIdx.x * 128 * DD;
    }
    Ahi += aOff; if (NTERMS == 3) Alo += aOff;
    Bhi += bOff; if (NTERMS == 3) Blo += bOff;

    extern __shared__ char smem[];
    const uint32_t sbase = smem_u32(smem);

    const int tid  = threadIdx.x;
    const int lane = tid & 31;
    const int wid  = tid >> 5;
    const int wm   = wid & 3;
    const int wn   = wid >> 2;
    const int sub  = lane >> 3;
    const int r8   = lane & 7;

    const uint32_t rowA  = wm * 32 + (sub & 1) * 8 + r8;
    const uint32_t colA  = (sub >> 1) * 8;
    const uint32_t rowB8 = (sub & 1) * 8 + r8;
    const uint32_t colB  = wn * 32 + (sub >> 1) * 8;

    float acc[2][4][4];
#pragma unroll
    for (int i = 0; i < 2; i++)
#pragma unroll
        for (int j = 0; j < 4; j++)
#pragma unroll
            for (int k = 0; k < 4; k++) acc[i][j][k] = 0.f;

    auto issue = [&](int c, int stg) {
        if (c < NC) {
            const uint32_t sb = sbase + (uint32_t)stg * STAGE;
            const int k0 = c * 64;
#pragma unroll
            for (int p = 0; p < 2 * NH; p++) {
                int i = tid + p * 512;
                int half = i >> 10, rem = i & 1023, row = rem >> 3, ch = rem & 7;
                const __half* s = (half ? Alo : Ahi) + (size_t)row * KA + k0 + ch * 8;
                cp_async16(sb + half * A_SEC + row * 144 + ch * 16, s);
            }
#pragma unroll
            for (int p = 0; p < 2 * NH; p++) {
                int i = tid + p * 512;
                int half = i >> 10, rem = i & 1023, row = rem >> 4, ch = rem & 15;
                const __half* s = (half ? Blo : Bhi) + (size_t)(k0 + row) * DD + ch * 8;
                cp_async16(sb + OFF_B + half * B_SEC + row * 272 + ch * 16, s);
            }
        }
        CP_COMMIT();
    };

    issue(0, 0);
    issue(1, 1);
    CP_WAIT1();
    __syncthreads();

    for (int c = 0; c < NC; c++) {
        issue(c + 2, (c + 2) % 3);
        const uint32_t st = sbase + (uint32_t)(c % 3) * STAGE;

#pragma unroll
        for (int ks = 0; ks < 4; ks++) {
            uint32_t ah[2][4], al[2][4], bh[2][4], bl[2][4];
#pragma unroll
            for (int mb = 0; mb < 2; mb++) {
                uint32_t ad = st + (rowA + mb * 16) * 144 + (ks * 16 + colA) * 2;
                ldsm_x4(ah[mb], ad);
                if (NTERMS == 3) ldsm_x4(al[mb], ad + A_SEC);
            }
#pragma unroll
            for (int g = 0; g < 2; g++) {
                uint32_t bd = st + OFF_B + (ks * 16 + rowB8) * 272 + (colB + g * 16) * 2;
                ldsm_x4_t(bh[g], bd);
                if (NTERMS == 3) ldsm_x4_t(bl[g], bd + B_SEC);
            }
#pragma unroll
            for (int mb = 0; mb < 2; mb++)
#pragma unroll
                for (int nb = 0; nb < 4; nb++)
                    mma_fp16(acc[mb][nb], ah[mb], &bh[nb >> 1][(nb & 1) * 2]);
            if (NTERMS == 3) {
#pragma unroll
                for (int mb = 0; mb < 2; mb++)
#pragma unroll
                    for (int nb = 0; nb < 4; nb++)
                        mma_fp16(acc[mb][nb], ah[mb], &bl[nb >> 1][(nb & 1) * 2]);
#pragma unroll
                for (int mb = 0; mb < 2; mb++)
#pragma unroll
                    for (int nb = 0; nb < 4; nb++)
                        mma_fp16(acc[mb][nb], al[mb], &bh[nb >> 1][(nb & 1) * 2]);
            }
        }
        CP_WAIT1();
        __syncthreads();
    }

    const int er = lane >> 2;
    const int ec = (lane & 3) * 2;
    float s8[8], q8[8];
    if (BIASED) {
#pragma unroll
        for (int i = 0; i < 8; i++) { s8[i] = 0.f; q8[i] = 0.f; }
    }
#pragma unroll
    for (int mb = 0; mb < 2; mb++)
#pragma unroll
        for (int nb = 0; nb < 4; nb++) {
            int row = wm * 32 + mb * 16 + er;
            int col = wn * 32 + nb * 8 + ec;
            float2 v0 = make_float2(acc[mb][nb][0], acc[mb][nb][1]);
            float2 v1 = make_float2(acc[mb][nb][2], acc[mb][nb][3]);
            if (BIASED) {
                float bx = bias[col], by = bias[col + 1];
                v0.x += bx; v0.y += by; v1.x += bx; v1.y += by;
                s8[nb * 2 + 0] += v0.x + v1.x;
                s8[nb * 2 + 1] += v0.y + v1.y;
                q8[nb * 2 + 0] += v0.x * v0.x + v1.x * v1.x;
                q8[nb * 2 + 1] += v0.y * v0.y + v1.y * v1.y;
                *reinterpret_cast<float2*>(outF + oOff + (size_t)row * DD + col) = v0;
                *reinterpret_cast<float2*>(outF + oOff + (size_t)(row + 8) * DD + col) = v1;
            } else {
                __half h0 = __float2half_rn(v0.x), h1 = __float2half_rn(v0.y);
                __half h2 = __float2half_rn(v1.x), h3 = __float2half_rn(v1.y);
                uint32_t hi0 = pack_f16(v0.x, v0.y);
                uint32_t hi1 = pack_f16(v1.x, v1.y);
                uint32_t lo0 = pack_f16(v0.x - __half2float(h0), v0.y - __half2float(h1));
                uint32_t lo1 = pack_f16(v1.x - __half2float(h2), v1.y - __half2float(h3));
                *reinterpret_cast<uint32_t*>(outHi + oOff + (size_t)row * DD + col) = hi0;
                *reinterpret_cast<uint32_t*>(outLo + oOff + (size_t)row * DD + col) = lo0;
                *reinterpret_cast<uint32_t*>(outHi + oOff + (size_t)(row + 8) * DD + col) = hi1;
                *reinterpret_cast<uint32_t*>(outLo + oOff + (size_t)(row + 8) * DD + col) = lo1;
            }
        }

    if (BIASED) {
#pragma unroll
        for (int off = 4; off < 32; off <<= 1) {
#pragma unroll
            for (int i = 0; i < 8; i++) {
                s8[i] += __shfl_xor_sync(0xFFFFFFFF, s8[i], off);
                q8[i] += __shfl_xor_sync(0xFFFFFFFF, q8[i], off);
            }
        }
        float* sBuf = reinterpret_cast<float*>(smem + SBUF_OFF);
        float* qBuf = sBuf + 4 * DD;
        if (lane < 4) {
#pragma unroll
            for (int nb = 0; nb < 4; nb++) {
#pragma unroll
                for (int j = 0; j < 2; j++) {
                    int col = wn * 32 + nb * 8 + lane * 2 + j;
                    sBuf[wm * DD + col] = s8[nb * 2 + j];
                    qBuf[wm * DD + col] = q8[nb * 2 + j];
                }
            }
        }
        __syncthreads();
        if (tid < DD) {
            float s = sBuf[tid] + sBuf[DD + tid] + sBuf[2 * DD + tid] + sBuf[3 * DD + tid];
            float q = qBuf[tid] + qBuf[DD + tid] + qBuf[2 * DD + tid] + qBuf[3 * DD + tid];
            pS[blockIdx.x * DD + tid] = s;
            pQ[blockIdx.x * DD + tid] = q;
        }
    }
}

// =================================================================
// W2 GEMM with fused inner-BN (unchanged).
// =================================================================
#define W2_AB    36864
#define W2_BOFF  73728
#define W2_BSTG  34816
#define W2_AUX   143360
#define W2_RED   144384
#define W2_SMEM  148480

__global__ __launch_bounds__(512)
void gemm_w2_fused(const float* __restrict__ Az,
                   const __half* __restrict__ Bhi,
                   const __half* __restrict__ Blo,
                   const float* __restrict__ bias,
                   const float* __restrict__ gamma, const float* __restrict__ beta,
                   const float* __restrict__ pSin, const float* __restrict__ pQin,
                   float* __restrict__ outF,
                   float* __restrict__ pSout, float* __restrict__ pQout) {
    const size_t aOff = (size_t)blockIdx.x * 128 * DD;
    Az += aOff;

    extern __shared__ char smem[];
    const uint32_t sbase = smem_u32(smem);

    const int tid  = threadIdx.x;
    const int lane = tid & 31;
    const int wid  = tid >> 5;
    const int wm   = wid & 3;
    const int wn   = wid >> 2;
    const int sub  = lane >> 3;
    const int r8   = lane & 7;

    const uint32_t rowA  = wm * 32 + (sub & 1) * 8 + r8;
    const uint32_t colA  = (sub >> 1) * 8;
    const uint32_t rowB8 = (sub & 1) * 8 + r8;
    const uint32_t colB  = wn * 32 + (sub >> 1) * 8;

    const int aRow[4] = { (tid) >> 4, (tid + 512) >> 4, (tid + 1024) >> 4, (tid + 1536) >> 4 };
    const int aSeg = tid & 15;

    float acc[2][4][4];
#pragma unroll
    for (int i = 0; i < 2; i++)
#pragma unroll
        for (int j = 0; j < 4; j++)
#pragma unroll
            for (int k = 0; k < 4; k++) acc[i][j][k] = 0.f;

    auto issueB = [&](int c) {
        const uint32_t sb = sbase + W2_BOFF + (uint32_t)(c & 1) * W2_BSTG;
#pragma unroll
        for (int p = 0; p < 4; p++) {
            int i = tid + p * 512;
            int half = i >> 10, rem = i & 1023, row = rem >> 4, ch = rem & 15;
            const __half* s = (half ? Blo : Bhi) + (size_t)(c * 64 + row) * DD + ch * 8;
            cp_async16(sb + half * 17408 + row * 272 + ch * 16, s);
        }
    };
    float4 aR[4];
    auto loadA = [&](int c) {
#pragma unroll
        for (int p = 0; p < 4; p++)
            aR[p] = *reinterpret_cast<const float4*>(Az + (size_t)aRow[p] * DD + c * 64 + aSeg * 4);
    };
    float* scl = reinterpret_cast<float*>(smem + W2_AUX);
    float* shf = scl + DD;
    auto convertBN = [&](int cc) {
        char* dhi = smem + (cc & 1) * W2_AB;
        char* dlo = dhi + 18432;
        const int col0 = cc * 64 + aSeg * 4;
        float4 sc = *reinterpret_cast<const float4*>(&scl[col0]);
        float4 sh = *reinterpret_cast<const float4*>(&shf[col0]);
#pragma unroll
        for (int p = 0; p < 4; p++) {
            float4 v = aR[p];
            float4 r;
            r.x = fmaxf(fmaf(v.x, sc.x, sh.x), 0.f);
            r.y = fmaxf(fmaf(v.y, sc.y, sh.y), 0.f);
            r.z = fmaxf(fmaf(v.z, sc.z, sh.z), 0.f);
            r.w = fmaxf(fmaf(v.w, sc.w, sh.w), 0.f);
            __half h0 = __float2half_rn(r.x), h1 = __float2half_rn(r.y);
            __half h2 = __float2half_rn(r.z), h3 = __float2half_rn(r.w);
            uint2 hv, lv;
            hv.x = pack_f16(r.x, r.y); hv.y = pack_f16(r.z, r.w);
            lv.x = pack_f16(r.x - __half2float(h0), r.y - __half2float(h1));
            lv.y = pack_f16(r.z - __half2float(h2), r.w - __half2float(h3));
            *reinterpret_cast<uint2*>(dhi + aRow[p] * 144 + aSeg * 8) = hv;
            *reinterpret_cast<uint2*>(dlo + aRow[p] * 144 + aSeg * 8) = lv;
        }
    };

    issueB(0); CP_COMMIT();
    issueB(1); CP_COMMIT();
    loadA(0);

    {
        float* rS = reinterpret_cast<float*>(smem + W2_RED);
        float* rQ = rS + 4 * DD;
        const int col = tid & 127, grp = tid >> 7;
        float s = 0.f, q = 0.f;
        for (int p = grp; p < BN_BLOCKS; p += 4) {
            s += pSin[p * DD + col];
            q += pQin[p * DD + col];
        }
        rS[grp * DD + col] = s;
        rQ[grp * DD + col] = q;
        __syncthreads();
        if (tid < DD) {
            float S = rS[tid] + rS[DD + tid] + rS[2 * DD + tid] + rS[3 * DD + tid];
            float Q = rQ[tid] + rQ[DD + tid] + rQ[2 * DD + tid] + rQ[3 * DD + tid];
            const float inv_m = 1.0f / (float)MTOT;
            float mean = S * inv_m;
            float var  = Q * inv_m - mean * mean;
            float sc   = gamma[tid] * rsqrtf(var + BN_EPS);
            scl[tid] = sc;
            shf[tid] = beta[tid] - mean * sc;
        }
        __syncthreads();
    }

    convertBN(0);
    CP_WAIT1();
    __syncthreads();

    loadA(1);

    {
        const uint32_t stA = sbase;
        const uint32_t stB = sbase + W2_BOFF;
#pragma unroll
        for (int ks = 0; ks < 4; ks++) {
            uint32_t ah[2][4], al[2][4], bh[2][4], bl[2][4];
#pragma unroll
            for (int mb = 0; mb < 2; mb++) {
                uint32_t ad = stA + (rowA + mb * 16) * 144 + (ks * 16 + colA) * 2;
                ldsm_x4(ah[mb], ad);
                ldsm_x4(al[mb], ad + 18432);
            }
#pragma unroll
            for (int g = 0; g < 2; g++) {
                uint32_t bd = stB + (ks * 16 + rowB8) * 272 + (colB + g * 16) * 2;
                ldsm_x4_t(bh[g], bd);
                ldsm_x4_t(bl[g], bd + 17408);
            }
#pragma unroll
            for (int mb = 0; mb < 2; mb++)
#pragma unroll
                for (int nb = 0; nb < 4; nb++)
                    mma_fp16(acc[mb][nb], ah[mb], &bh[nb >> 1][(nb & 1) * 2]);
#pragma unroll
            for (int mb = 0; mb < 2; mb++)
#pragma unroll
                for (int nb = 0; nb < 4; nb++)
                    mma_fp16(acc[mb][nb], ah[mb], &bl[nb >> 1][(nb & 1) * 2]);
#pragma unroll
            for (int mb = 0; mb < 2; mb++)
#pragma unroll
                for (int nb = 0; nb < 4; nb++)
                    mma_fp16(acc[mb][nb], al[mb], &bh[nb >> 1][(nb & 1) * 2]);
        }
    }

    convertBN(1);
    CP_WAIT0();
    __syncthreads();

    {
        const uint32_t stA = sbase + W2_AB;
        const uint32_t stB = sbase + W2_BOFF + W2_BSTG;
#pragma unroll
        for (int ks = 0; ks < 4; ks++) {
            uint32_t ah[2][4], al[2][4], bh[2][4], bl[2][4];
#pragma unroll
            for (int mb = 0; mb < 2; mb++) {
                uint32_t ad = stA + (rowA + mb * 16) * 144 + (ks * 16 + colA) * 2;
                ldsm_x4(ah[mb], ad);
                ldsm_x4(al[mb], ad + 18432);
            }
#pragma unroll
            for (int g = 0; g < 2; g++) {
                uint32_t bd = stB + (ks * 16 + rowB8) * 272 + (colB + g * 16) * 2;
                ldsm_x4_t(bh[g], bd);
                ldsm_x4_t(bl[g], bd + 17408);
            }
#pragma unroll
            for (int mb = 0; mb < 2; mb++)
#pragma unroll
                for (int nb = 0; nb < 4; nb++)
                    mma_fp16(acc[mb][nb], ah[mb], &bh[nb >> 1][(nb & 1) * 2]);
#pragma unroll
            for (int mb = 0; mb < 2; mb++)
#pragma unroll
                for (int nb = 0; nb < 4; nb++)
                    mma_fp16(acc[mb][nb], ah[mb], &bl[nb >> 1][(nb & 1) * 2]);
#pragma unroll
            for (int mb = 0; mb < 2; mb++)
#pragma unroll
                for (int nb = 0; nb < 4; nb++)
                    mma_fp16(acc[mb][nb], al[mb], &bh[nb >> 1][(nb & 1) * 2]);
        }
    }
    __syncthreads();

    const int er = lane >> 2;
    const int ec = (lane & 3) * 2;
    float s8[8], q8[8];
#pragma unroll
    for (int i = 0; i < 8; i++) { s8[i] = 0.f; q8[i] = 0.f; }
#pragma unroll
    for (int mb = 0; mb < 2; mb++)
#pragma unroll
        for (int nb = 0; nb < 4; nb++) {
            int row = wm * 32 + mb * 16 + er;
            int col = wn * 32 + nb * 8 + ec;
            float2 v0 = make_float2(acc[mb][nb][0], acc[mb][nb][1]);
            float2 v1 = make_float2(acc[mb][nb][2], acc[mb][nb][3]);
            float bx = bias[col], by = bias[col + 1];
            v0.x += bx; v0.y += by; v1.x += bx; v1.y += by;
            s8[nb * 2 + 0] += v0.x + v1.x;
            s8[nb * 2 + 1] += v0.y + v1.y;
            q8[nb * 2 + 0] += v0.x * v0.x + v1.x * v1.x;
            q8[nb * 2 + 1] += v0.y * v0.y + v1.y * v1.y;
            *reinterpret_cast<float2*>(outF + aOff + (size_t)row * DD + col) = v0;
            *reinterpret_cast<float2*>(outF + aOff + (size_t)(row + 8) * DD + col) = v1;
        }

#pragma unroll
    for (int off = 4; off < 32; off <<= 1) {
#pragma unroll
        for (int i = 0; i < 8; i++) {
            s8[i] += __shfl_xor_sync(0xFFFFFFFF, s8[i], off);
            q8[i] += __shfl_xor_sync(0xFFFFFFFF, q8[i], off);
        }
    }
    float* sBuf = reinterpret_cast<float*>(smem + W2_RED);
    float* qBuf = sBuf + 4 * DD;
    if (lane < 4) {
#pragma unroll
        for (int nb = 0; nb < 4; nb++) {
#pragma unroll
            for (int j = 0; j < 2; j++) {
                int col = wn * 32 + nb * 8 + lane * 2 + j;
                sBuf[wm * DD + col] = s8[nb * 2 + j];
                qBuf[wm * DD + col] = q8[nb * 2 + j];
            }
        }
    }
    __syncthreads();
    if (tid < DD) {
        float s = sBuf[tid] + sBuf[DD + tid] + sBuf[2 * DD + tid] + sBuf[3 * DD + tid];
        float q = qBuf[tid] + qBuf[DD + tid] + qBuf[2 * DD + tid] + qBuf[3 * DD + tid];
        pSout[blockIdx.x * DD + tid] = s;
        pQout[blockIdx.x * DD + tid] = q;
    }
}

// =================================================================
// Merged preprocessing (FIXED grid coverage):
// blocks [0,4096): x fp32->fp16 hi (4096*256 float4 = full x)
// blocks [4096,4128): W1 split (32*256 float4 = LL*DD*DD/4)
// blocks [4128,4160): W2 split
// =================================================================
#define PRE_XBLK 4096
#define PRE_WBLK 32

__global__ __launch_bounds__(256)
void preprocess_kernel(const float* __restrict__ x,
                       const float* __restrict__ W1, const float* __restrict__ W2,
                       __half* __restrict__ hHi,
                       __half* __restrict__ W1Hi, __half* __restrict__ W1Lo,
                       __half* __restrict__ W2Hi, __half* __restrict__ W2Lo) {
    const int b = blockIdx.x;
    if (b < PRE_XBLK) {
        const size_t idx = (size_t)b * 256 + threadIdx.x;
        float4 v = reinterpret_cast<const float4*>(x)[idx];
        uint2 hv;
        hv.x = pack_f16(v.x, v.y); hv.y = pack_f16(v.z, v.w);
        reinterpret_cast<uint2*>(hHi)[idx] = hv;
    } else {
        const bool w2 = (b >= PRE_XBLK + PRE_WBLK);
        const float* src = w2 ? W2 : W1;
        __half* hi = w2 ? W2Hi : W1Hi;
        __half* lo = w2 ? W2Lo : W1Lo;
        const size_t idx = (size_t)(b - (w2 ? PRE_XBLK + PRE_WBLK : PRE_XBLK)) * 256 + threadIdx.x;
        float4 v = reinterpret_cast<const float4*>(src)[idx];
        __half h0 = __float2half_rn(v.x), h1 = __float2half_rn(v.y);
        __half h2 = __float2half_rn(v.z), h3 = __float2half_rn(v.w);
        uint2 hv, lv;
        hv.x = pack_f16(v.x, v.y); hv.y = pack_f16(v.z, v.w);
        lv.x = pack_f16(v.x - __half2float(h0), v.y - __half2float(h1));
        lv.y = pack_f16(v.z - __half2float(h2), v.w - __half2float(h3));
        reinterpret_cast<uint2*>(hi)[idx] = hv;
        reinterpret_cast<uint2*>(lo)[idx] = lv;
    }
}

// =================================================================
// Outer-BN stats+apply (unchanged).
// =================================================================
template <int MODE>
__global__ __launch_bounds__(256)
void bn_stats_apply(const float* __restrict__ gamma, const float* __restrict__ beta,
                    const float* __restrict__ pS, const float* __restrict__ pQ,
                    const float* __restrict__ x,
                    float* __restrict__ outF, __half* __restrict__ yhi) {
    __shared__ float sS[2][DD], sQ[2][DD];
    __shared__ float scl[DD], shf[DD];
    const int tid  = threadIdx.x;
    const int col  = tid & 127;
    const int half = tid >> 7;

    float s = 0.f, q = 0.f;
    for (int p = half; p < BN_BLOCKS; p += 2) {
        s += pS[p * DD + col];
        q += pQ[p * DD + col];
    }
    sS[half][col] = s;
    sQ[half][col] = q;
    __syncthreads();
    if (tid < DD) {
        float S = sS[0][tid] + sS[1][tid];
        float Q = sQ[0][tid] + sQ[1][tid];
        const float inv_m = 1.0f / (float)MTOT;
        float mean = S * inv_m;
        float var  = Q * inv_m - mean * mean;
        float sc   = gamma[tid] * rsqrtf(var + BN_EPS);
        scl[tid] = sc;
        shf[tid] = beta[tid] - mean * sc;
    }
    __syncthreads();

    const int base = blockIdx.x * 8192;
#pragma unroll 8
    for (int i = 0; i < 32; i++) {
        int idx = base + i * 256 + tid;
        int c4  = idx & 31;
        float4 v = reinterpret_cast<const float4*>(x)[idx];
        float4 sc = *reinterpret_cast<const float4*>(&scl[c4 * 4]);
        float4 sh = *reinterpret_cast<const float4*>(&shf[c4 * 4]);
        float4 r;
        r.x = fmaxf(fmaf(v.x, sc.x, sh.x), 0.f);
        r.y = fmaxf(fmaf(v.y, sc.y, sh.y), 0.f);
        r.z = fmaxf(fmaf(v.z, sc.z, sh.z), 0.f);
        r.w = fmaxf(fmaf(v.w, sc.w, sh.w), 0.f);
        if (MODE == 1) {
            reinterpret_cast<float4*>(outF)[idx] = r;
        } else {
            uint2 hv;
            hv.x = pack_f16(r.x, r.y); hv.y = pack_f16(r.z, r.w);
            reinterpret_cast<uint2*>(yhi)[idx] = hv;
        }
    }
}

// ---------------- launch ----------------
extern "C" void kernel_launch(void* const* d_in, const int* in_sizes, int n_in,
                              void* d_out, int out_size) {
    const float* x     = (const float*)d_in[0];
    const float* adj   = (const float*)d_in[2];
    const float* W1    = (const float*)d_in[3];
    const float* b1    = (const float*)d_in[4];
    const float* W2    = (const float*)d_in[5];
    const float* b2    = (const float*)d_in[6];
    const float* g_in   = (const float*)d_in[7];
    const float* be_in  = (const float*)d_in[8];
    const float* g_out  = (const float*)d_in[9];
    const float* be_out = (const float*)d_in[10];
    float* out = (float*)d_out;

    __half *adjH, *hHi, *pHi, *pLo, *W1Hi, *W1Lo, *W2Hi, *W2Lo;
    float *z, *pS1, *pQ1, *pS2, *pQ2;
    cudaGetSymbolAddress((void**)&adjH, g_adjH);
    cudaGetSymbolAddress((void**)&hHi, g_hHi);
    cudaGetSymbolAddress((void**)&pHi, g_pHi);
    cudaGetSymbolAddress((void**)&pLo, g_pLo);
    cudaGetSymbolAddress((void**)&W1Hi, g_W1Hi);
    cudaGetSymbolAddress((void**)&W1Lo, g_W1Lo);
    cudaGetSymbolAddress((void**)&W2Hi, g_W2Hi);
    cudaGetSymbolAddress((void**)&W2Lo, g_W2Lo);
    cudaGetSymbolAddress((void**)&z, g_z);
    cudaGetSymbolAddress((void**)&pS1, g_partS1);
    cudaGetSymbolAddress((void**)&pQ1, g_partQ1);
    cudaGetSymbolAddress((void**)&pS2, g_partS2);
    cudaGetSymbolAddress((void**)&pQ2, g_partQ2);

    constexpr int SMEM3B = 3 * (2 * 128 * 144 + 2 * 64 * 272) + 4096;  // 219136
    constexpr int SMEM1  = 3 * (128 * 144 + 64 * 272);                 // 107520
    cudaFuncSetAttribute((const void*)gemm_pool_convert,
                         cudaFuncAttributeMaxDynamicSharedMemorySize, POOL_SMEM);
    cudaFuncSetAttribute((const void*)gemm_f16<NN, 1, false, 2>,
                         cudaFuncAttributeMaxDynamicSharedMemorySize, SMEM1);
    cudaFuncSetAttribute((const void*)gemm_f16<DD, 3, true, 1>,
                         cudaFuncAttributeMaxDynamicSharedMemorySize, SMEM3B);
    cudaFuncSetAttribute((const void*)gemm_w2_fused,
                         cudaFuncAttributeMaxDynamicSharedMemorySize, W2_SMEM);

    preprocess_kernel<<<PRE_XBLK + 2 * PRE_WBLK, 256>>>(
        x, W1, W2, hHi, W1Hi, W1Lo, W2Hi, W2Lo);

    const dim3 gridPool(NN / 128, BATCH);
    const int  gridW = MTOT / 128;

    for (int l = 0; l < LL; l++) {
        if (l == 0)
            gemm_pool_convert<<<gridPool, 512, POOL_SMEM>>>(
                adj, hHi, adjH, pHi, pLo);
        else
            gemm_f16<NN, 1, false, 2><<<gridPool, 512, SMEM1>>>(
                adjH, nullptr, hHi, nullptr,
                nullptr, nullptr, pHi, pLo, nullptr, nullptr);

        gemm_f16<DD, 3, true, 1><<<gridW, 512, SMEM3B>>>(
            pHi, pLo, W1Hi + (size_t)l * DD * DD, W1Lo + (size_t)l * DD * DD,
            b1 + (size_t)l * DD, z, nullptr, nullptr, pS1, pQ1);

        gemm_w2_fused<<<gridW, 512, W2_SMEM>>>(
            z, W2Hi + (size_t)l * DD * DD, W2Lo + (size_t)l * DD * DD,
            b2 + (size_t)l * DD, g_in + (size_t)l * DD, be_in + (size_t)l * DD,
            pS1, pQ1, z, pS2, pQ2);

        if (l == LL - 1)
            bn_stats_apply<1><<<128, 256>>>(
                g_out + (size_t)l * DD, be_out + (size_t)l * DD, pS2, pQ2,
                z, out, nullptr);
        else
            bn_stats_apply<0><<<128, 256>>>(
                g_out + (size_t)l * DD, be_out + (size_t)l * DD, pS2, pQ2,
                z, nullptr, hHi);
    }
}

// round 16
// speedup vs baseline: 1.0678x; 1.0678x over previous
#include <cuda_runtime.h>
#include <cuda_fp16.h>
#include <cstdint>

#define BATCH 32
#define NN    1024
#define DD    128
#define LL    2
#define MTOT  (BATCH * NN)
#define BN_EPS 1e-5f
#define BN_BLOCKS 256

// ---------------- scratch ----------------
__device__ __half g_adjH[(size_t)BATCH * NN * NN];
__device__ __half g_hHi[MTOT * DD];
__device__ __half g_pHi[MTOT * DD];
__device__ __half g_pLo[MTOT * DD];
__device__ __half g_W1Hi[LL * DD * DD];
__device__ __half g_W1Lo[LL * DD * DD];
__device__ __half g_W2Hi[LL * DD * DD];
__device__ __half g_W2Lo[LL * DD * DD];
__device__ float g_z[MTOT * DD];
__device__ float g_partS1[BN_BLOCKS * DD];
__device__ float g_partQ1[BN_BLOCKS * DD];
__device__ float g_partS2[BN_BLOCKS * DD];
__device__ float g_partQ2[BN_BLOCKS * DD];

// ---------------- helpers ----------------
__device__ __forceinline__ uint32_t smem_u32(const void* p) {
    uint32_t a;
    asm("{ .reg .u64 t; cvta.to.shared.u64 t, %1; cvt.u32.u64 %0, t; }" : "=r"(a) : "l"(p));
    return a;
}
__device__ __forceinline__ void ldsm_x4(uint32_t* r, uint32_t addr) {
    asm volatile("ldmatrix.sync.aligned.m8n8.x4.shared.b16 {%0,%1,%2,%3}, [%4];"
                 : "=r"(r[0]), "=r"(r[1]), "=r"(r[2]), "=r"(r[3]) : "r"(addr));
}
__device__ __forceinline__ void ldsm_x4_t(uint32_t* r, uint32_t addr) {
    asm volatile("ldmatrix.sync.aligned.m8n8.x4.trans.shared.b16 {%0,%1,%2,%3}, [%4];"
                 : "=r"(r[0]), "=r"(r[1]), "=r"(r[2]), "=r"(r[3]) : "r"(addr));
}
__device__ __forceinline__ void mma_fp16(float* c, const uint32_t* a, const uint32_t* b) {
    asm volatile(
        "mma.sync.aligned.m16n8k16.row.col.f32.f16.f16.f32 "
        "{%0,%1,%2,%3}, {%4,%5,%6,%7}, {%8,%9}, {%0,%1,%2,%3};"
        : "+f"(c[0]), "+f"(c[1]), "+f"(c[2]), "+f"(c[3])
        : "r"(a[0]), "r"(a[1]), "r"(a[2]), "r"(a[3]), "r"(b[0]), "r"(b[1]));
}
__device__ __forceinline__ void cp_async16(uint32_t dst, const void* src) {
    asm volatile("cp.async.cg.shared.global [%0], [%1], 16;" :: "r"(dst), "l"(src));
}
#define CP_COMMIT() asm volatile("cp.async.commit_group;" ::: "memory")
#define CP_WAIT1()  asm volatile("cp.async.wait_group 1;"  ::: "memory")
#define CP_WAIT0()  asm volatile("cp.async.wait_group 0;"  ::: "memory")

__device__ __forceinline__ uint32_t pack_f16(float x, float y) {
    __half2 t = __floats2half2_rn(x, y);
    return *reinterpret_cast<uint32_t*>(&t);
}

// =================================================================
// Pool layer-1 GEMM (fp16, 1 term), 1 CTA/SM — R13 config (best).
// Register-staged convert overlapped under the MMA body.
// =================================================================
#define AH_BUF   18432
#define PB_OFF   36864
#define PB_STG   17408
#define POOL_SMEM 89088

__global__ __launch_bounds__(512)
void gemm_pool_convert(const float* __restrict__ A,
                       const __half* __restrict__ Bhi,
                       __half* __restrict__ adjHOut,
                       __half* __restrict__ outHi,
                       __half* __restrict__ outLo) {
    constexpr int NC = NN / 64;

    const size_t aOff = (size_t)blockIdx.y * NN * NN + (size_t)blockIdx.x * 128 * NN;
    const size_t bOff = (size_t)blockIdx.y * NN * DD;
    const size_t oOff = (size_t)blockIdx.y * NN * DD + (size_t)blockIdx.x * 128 * DD;
    A += aOff;
    adjHOut += aOff;
    Bhi += bOff;

    extern __shared__ char smem[];
    const uint32_t sbase = smem_u32(smem);

    const int tid  = threadIdx.x;
    const int lane = tid & 31;
    const int wid  = tid >> 5;
    const int wm   = wid & 3;
    const int wn   = wid >> 2;
    const int sub  = lane >> 3;
    const int r8   = lane & 7;

    const uint32_t rowA  = wm * 32 + (sub & 1) * 8 + r8;
    const uint32_t colA  = (sub >> 1) * 8;
    const uint32_t rowB8 = (sub & 1) * 8 + r8;
    const uint32_t colB  = wn * 32 + (sub >> 1) * 8;

    const int aRow[4] = { (tid) >> 4, (tid + 512) >> 4, (tid + 1024) >> 4, (tid + 1536) >> 4 };
    const int aSeg = tid & 15;

    float acc[2][4][4];
#pragma unroll
    for (int i = 0; i < 2; i++)
#pragma unroll
        for (int j = 0; j < 4; j++)
#pragma unroll
            for (int k = 0; k < 4; k++) acc[i][j][k] = 0.f;

    auto issueB = [&](int c) {
        const uint32_t sb = sbase + PB_OFF + (uint32_t)(c % 3) * PB_STG;
#pragma unroll
        for (int p = 0; p < 2; p++) {
            int i = tid + p * 512;
            int row = i >> 4, ch = i & 15;
            cp_async16(sb + row * 272 + ch * 16, Bhi + (size_t)(c * 64 + row) * DD + ch * 8);
        }
    };
    float4 aR[4];
    auto loadA = [&](int c) {
#pragma unroll
        for (int p = 0; p < 4; p++)
            aR[p] = *reinterpret_cast<const float4*>(A + (size_t)aRow[p] * NN + c * 64 + aSeg * 4);
    };
    auto convert = [&](int cc) {
        char* dhi = smem + (cc & 1) * AH_BUF;
#pragma unroll
        for (int p = 0; p < 4; p++) {
            float4 v = aR[p];
            uint2 hv;
            hv.x = pack_f16(v.x, v.y);
            hv.y = pack_f16(v.z, v.w);
            *reinterpret_cast<uint2*>(dhi + aRow[p] * 144 + aSeg * 8) = hv;
            *reinterpret_cast<uint2*>(adjHOut + (size_t)aRow[p] * NN + cc * 64 + aSeg * 4) = hv;
        }
    };

    loadA(0);
    issueB(0); CP_COMMIT();
    issueB(1); CP_COMMIT();
    convert(0);
    CP_WAIT1();
    __syncthreads();

    for (int c = 0; c < NC; c++) {
        if (c + 1 < NC) loadA(c + 1);
        if (c + 2 < NC) issueB(c + 2);
        CP_COMMIT();

        const uint32_t stA = sbase + (uint32_t)(c & 1) * AH_BUF;
        const uint32_t stB = sbase + PB_OFF + (uint32_t)(c % 3) * PB_STG;
#pragma unroll
        for (int ks = 0; ks < 4; ks++) {
            uint32_t ah[2][4], bh[2][4];
#pragma unroll
            for (int mb = 0; mb < 2; mb++) {
                uint32_t ad = stA + (rowA + mb * 16) * 144 + (ks * 16 + colA) * 2;
                ldsm_x4(ah[mb], ad);
            }
#pragma unroll
            for (int g = 0; g < 2; g++) {
                uint32_t bd = stB + (ks * 16 + rowB8) * 272 + (colB + g * 16) * 2;
                ldsm_x4_t(bh[g], bd);
            }
#pragma unroll
            for (int mb = 0; mb < 2; mb++)
#pragma unroll
                for (int nb = 0; nb < 4; nb++)
                    mma_fp16(acc[mb][nb], ah[mb], &bh[nb >> 1][(nb & 1) * 2]);
        }

        if (c + 1 < NC) convert(c + 1);

        CP_WAIT1();
        __syncthreads();
    }

    const int er = lane >> 2;
    const int ec = (lane & 3) * 2;
#pragma unroll
    for (int mb = 0; mb < 2; mb++)
#pragma unroll
        for (int nb = 0; nb < 4; nb++) {
            int row = wm * 32 + mb * 16 + er;
            int col = wn * 32 + nb * 8 + ec;
            float2 v0 = make_float2(acc[mb][nb][0], acc[mb][nb][1]);
            float2 v1 = make_float2(acc[mb][nb][2], acc[mb][nb][3]);
            __half h0 = __float2half_rn(v0.x), h1 = __float2half_rn(v0.y);
            __half h2 = __float2half_rn(v1.x), h3 = __float2half_rn(v1.y);
            uint32_t hi0 = pack_f16(v0.x, v0.y);
            uint32_t hi1 = pack_f16(v1.x, v1.y);
            uint32_t lo0 = pack_f16(v0.x - __half2float(h0), v0.y - __half2float(h1));
            uint32_t lo1 = pack_f16(v1.x - __half2float(h2), v1.y - __half2float(h3));
            *reinterpret_cast<uint32_t*>(outHi + oOff + (size_t)row * DD + col) = hi0;
            *reinterpret_cast<uint32_t*>(outLo + oOff + (size_t)row * DD + col) = lo0;
            *reinterpret_cast<uint32_t*>(outHi + oOff + (size_t)(row + 8) * DD + col) = hi1;
            *reinterpret_cast<uint32_t*>(outLo + oOff + (size_t)(row + 8) * DD + col) = lo1;
        }
}

// =================================================================
// Unified fp16 GEMM (R13). MINB=2 only for pool L2 (fits regs).
// =================================================================
template <int KA, int NTERMS, bool BIASED, int MINB>
__global__ __launch_bounds__(512, MINB)
void gemm_f16(const __half* __restrict__ Ahi, const __half* __restrict__ Alo,
              const __half* __restrict__ Bhi, const __half* __restrict__ Blo,
              const float* __restrict__ bias,
              float* __restrict__ outF,
              __half* __restrict__ outHi, __half* __restrict__ outLo,
              float* __restrict__ pS, float* __restrict__ pQ) {
    constexpr int NC  = KA / 64;
    constexpr int NH  = (NTERMS == 3) ? 2 : 1;
    constexpr int A_SEC = 128 * 144;
    constexpr int B_SEC = 64 * 272;
    constexpr int OFF_B = NH * A_SEC;
    constexpr int STAGE = OFF_B + NH * B_SEC;
    constexpr int SBUF_OFF = 3 * STAGE;

    size_t aOff, bOff, oOff;
    if (KA == NN) {
        aOff = (size_t)blockIdx.y * NN * NN + (size_t)blockIdx.x * 128 * NN;
        bOff = (size_t)blockIdx.y * NN * DD;
        oOff = (size_t)blockIdx.y * NN * DD + (size_t)blockIdx.x * 128 * DD;
    } else {
        aOff = (size_t)blockIdx.x * 128 * DD;
        bOff = 0;
        oOff = (size_t)blockIdx.x * 128 * DD;
    }
    Ahi += aOff; if (NTERMS == 3) Alo += aOff;
    Bhi += bOff; if (NTERMS == 3) Blo += bOff;

    extern __shared__ char smem[];
    const uint32_t sbase = smem_u32(smem);

    const int tid  = threadIdx.x;
    const int lane = tid & 31;
    const int wid  = tid >> 5;
    const int wm   = wid & 3;
    const int wn   = wid >> 2;
    const int sub  = lane >> 3;
    const int r8   = lane & 7;

    const uint32_t rowA  = wm * 32 + (sub & 1) * 8 + r8;
    const uint32_t colA  = (sub >> 1) * 8;
    const uint32_t rowB8 = (sub & 1) * 8 + r8;
    const uint32_t colB  = wn * 32 + (sub >> 1) * 8;

    float acc[2][4][4];
#pragma unroll
    for (int i = 0; i < 2; i++)
#pragma unroll
        for (int j = 0; j < 4; j++)
#pragma unroll
            for (int k = 0; k < 4; k++) acc[i][j][k] = 0.f;

    auto issue = [&](int c, int stg) {
        if (c < NC) {
            const uint32_t sb = sbase + (uint32_t)stg * STAGE;
            const int k0 = c * 64;
#pragma unroll
            for (int p = 0; p < 2 * NH; p++) {
                int i = tid + p * 512;
                int half = i >> 10, rem = i & 1023, row = rem >> 3, ch = rem & 7;
                const __half* s = (half ? Alo : Ahi) + (size_t)row * KA + k0 + ch * 8;
                cp_async16(sb + half * A_SEC + row * 144 + ch * 16, s);
            }
#pragma unroll
            for (int p = 0; p < 2 * NH; p++) {
                int i = tid + p * 512;
                int half = i >> 10, rem = i & 1023, row = rem >> 4, ch = rem & 15;
                const __half* s = (half ? Blo : Bhi) + (size_t)(k0 + row) * DD + ch * 8;
                cp_async16(sb + OFF_B + half * B_SEC + row * 272 + ch * 16, s);
            }
        }
        CP_COMMIT();
    };

    issue(0, 0);
    issue(1, 1);
    CP_WAIT1();
    __syncthreads();

    for (int c = 0; c < NC; c++) {
        issue(c + 2, (c + 2) % 3);
        const uint32_t st = sbase + (uint32_t)(c % 3) * STAGE;

#pragma unroll
        for (int ks = 0; ks < 4; ks++) {
            uint32_t ah[2][4], al[2][4], bh[2][4], bl[2][4];
#pragma unroll
            for (int mb = 0; mb < 2; mb++) {
                uint32_t ad = st + (rowA + mb * 16) * 144 + (ks * 16 + colA) * 2;
                ldsm_x4(ah[mb], ad);
                if (NTERMS == 3) ldsm_x4(al[mb], ad + A_SEC);
            }
#pragma unroll
            for (int g = 0; g < 2; g++) {
                uint32_t bd = st + OFF_B + (ks * 16 + rowB8) * 272 + (colB + g * 16) * 2;
                ldsm_x4_t(bh[g], bd);
                if (NTERMS == 3) ldsm_x4_t(bl[g], bd + B_SEC);
            }
#pragma unroll
            for (int mb = 0; mb < 2; mb++)
#pragma unroll
                for (int nb = 0; nb < 4; nb++)
                    mma_fp16(acc[mb][nb], ah[mb], &bh[nb >> 1][(nb & 1) * 2]);
            if (NTERMS == 3) {
#pragma unroll
                for (int mb = 0; mb < 2; mb++)
#pragma unroll
                    for (int nb = 0; nb < 4; nb++)
                        mma_fp16(acc[mb][nb], ah[mb], &bl[nb >> 1][(nb & 1) * 2]);
#pragma unroll
                for (int mb = 0; mb < 2; mb++)
#pragma unroll
                    for (int nb = 0; nb < 4; nb++)
                        mma_fp16(acc[mb][nb], al[mb], &bh[nb >> 1][(nb & 1) * 2]);
            }
        }
        CP_WAIT1();
        __syncthreads();
    }

    const int er = lane >> 2;
    const int ec = (lane & 3) * 2;
    float s8[8], q8[8];
    if (BIASED) {
#pragma unroll
        for (int i = 0; i < 8; i++) { s8[i] = 0.f; q8[i] = 0.f; }
    }
#pragma unroll
    for (int mb = 0; mb < 2; mb++)
#pragma unroll
        for (int nb = 0; nb < 4; nb++) {
            int row = wm * 32 + mb * 16 + er;
            int col = wn * 32 + nb * 8 + ec;
            float2 v0 = make_float2(acc[mb][nb][0], acc[mb][nb][1]);
            float2 v1 = make_float2(acc[mb][nb][2], acc[mb][nb][3]);
            if (BIASED) {
                float bx = bias[col], by = bias[col + 1];
                v0.x += bx; v0.y += by; v1.x += bx; v1.y += by;
                s8[nb * 2 + 0] += v0.x + v1.x;
                s8[nb * 2 + 1] += v0.y + v1.y;
                q8[nb * 2 + 0] += v0.x * v0.x + v1.x * v1.x;
                q8[nb * 2 + 1] += v0.y * v0.y + v1.y * v1.y;
                *reinterpret_cast<float2*>(outF + oOff + (size_t)row * DD + col) = v0;
                *reinterpret_cast<float2*>(outF + oOff + (size_t)(row + 8) * DD + col) = v1;
            } else {
                __half h0 = __float2half_rn(v0.x), h1 = __float2half_rn(v0.y);
                __half h2 = __float2half_rn(v1.x), h3 = __float2half_rn(v1.y);
                uint32_t hi0 = pack_f16(v0.x, v0.y);
                uint32_t hi1 = pack_f16(v1.x, v1.y);
                uint32_t lo0 = pack_f16(v0.x - __half2float(h0), v0.y - __half2float(h1));
                uint32_t lo1 = pack_f16(v1.x - __half2float(h2), v1.y - __half2float(h3));
                *reinterpret_cast<uint32_t*>(outHi + oOff + (size_t)row * DD + col) = hi0;
                *reinterpret_cast<uint32_t*>(outLo + oOff + (size_t)row * DD + col) = lo0;
                *reinterpret_cast<uint32_t*>(outHi + oOff + (size_t)(row + 8) * DD + col) = hi1;
                *reinterpret_cast<uint32_t*>(outLo + oOff + (size_t)(row + 8) * DD + col) = lo1;
            }
        }

    if (BIASED) {
#pragma unroll
        for (int off = 4; off < 32; off <<= 1) {
#pragma unroll
            for (int i = 0; i < 8; i++) {
                s8[i] += __shfl_xor_sync(0xFFFFFFFF, s8[i], off);
                q8[i] += __shfl_xor_sync(0xFFFFFFFF, q8[i], off);
            }
        }
        float* sBuf = reinterpret_cast<float*>(smem + SBUF_OFF);
        float* qBuf = sBuf + 4 * DD;
        if (lane < 4) {
#pragma unroll
            for (int nb = 0; nb < 4; nb++) {
#pragma unroll
                for (int j = 0; j < 2; j++) {
                    int col = wn * 32 + nb * 8 + lane * 2 + j;
                    sBuf[wm * DD + col] = s8[nb * 2 + j];
                    qBuf[wm * DD + col] = q8[nb * 2 + j];
                }
            }
        }
        __syncthreads();
        if (tid < DD) {
            float s = sBuf[tid] + sBuf[DD + tid] + sBuf[2 * DD + tid] + sBuf[3 * DD + tid];
            float q = qBuf[tid] + qBuf[DD + tid] + qBuf[2 * DD + tid] + qBuf[3 * DD + tid];
            pS[blockIdx.x * DD + tid] = s;
            pQ[blockIdx.x * DD + tid] = q;
        }
    }
}

// =================================================================
// W2 GEMM with fused inner-BN (R13, unchanged).
// =================================================================
#define W2_AB    36864
#define W2_BOFF  73728
#define W2_BSTG  34816
#define W2_AUX   143360
#define W2_RED   144384
#define W2_SMEM  148480

__global__ __launch_bounds__(512)
void gemm_w2_fused(const float* __restrict__ Az,
                   const __half* __restrict__ Bhi,
                   const __half* __restrict__ Blo,
                   const float* __restrict__ bias,
                   const float* __restrict__ gamma, const float* __restrict__ beta,
                   const float* __restrict__ pSin, const float* __restrict__ pQin,
                   float* __restrict__ outF,
                   float* __restrict__ pSout, float* __restrict__ pQout) {
    const size_t aOff = (size_t)blockIdx.x * 128 * DD;
    Az += aOff;

    extern __shared__ char smem[];
    const uint32_t sbase = smem_u32(smem);

    const int tid  = threadIdx.x;
    const int lane = tid & 31;
    const int wid  = tid >> 5;
    const int wm   = wid & 3;
    const int wn   = wid >> 2;
    const int sub  = lane >> 3;
    const int r8   = lane & 7;

    const uint32_t rowA  = wm * 32 + (sub & 1) * 8 + r8;
    const uint32_t colA  = (sub >> 1) * 8;
    const uint32_t rowB8 = (sub & 1) * 8 + r8;
    const uint32_t colB  = wn * 32 + (sub >> 1) * 8;

    const int aRow[4] = { (tid) >> 4, (tid + 512) >> 4, (tid + 1024) >> 4, (tid + 1536) >> 4 };
    const int aSeg = tid & 15;

    float acc[2][4][4];
#pragma unroll
    for (int i = 0; i < 2; i++)
#pragma unroll
        for (int j = 0; j < 4; j++)
#pragma unroll
            for (int k = 0; k < 4; k++) acc[i][j][k] = 0.f;

    auto issueB = [&](int c) {
        const uint32_t sb = sbase + W2_BOFF + (uint32_t)(c & 1) * W2_BSTG;
#pragma unroll
        for (int p = 0; p < 4; p++) {
            int i = tid + p * 512;
            int half = i >> 10, rem = i & 1023, row = rem >> 4, ch = rem & 15;
            const __half* s = (half ? Blo : Bhi) + (size_t)(c * 64 + row) * DD + ch * 8;
            cp_async16(sb + half * 17408 + row * 272 + ch * 16, s);
        }
    };
    float4 aR[4];
    auto loadA = [&](int c) {
#pragma unroll
        for (int p = 0; p < 4; p++)
            aR[p] = *reinterpret_cast<const float4*>(Az + (size_t)aRow[p] * DD + c * 64 + aSeg * 4);
    };
    float* scl = reinterpret_cast<float*>(smem + W2_AUX);
    float* shf = scl + DD;
    auto convertBN = [&](int cc) {
        char* dhi = smem + (cc & 1) * W2_AB;
        char* dlo = dhi + 18432;
        const int col0 = cc * 64 + aSeg * 4;
        float4 sc = *reinterpret_cast<const float4*>(&scl[col0]);
        float4 sh = *reinterpret_cast<const float4*>(&shf[col0]);
#pragma unroll
        for (int p = 0; p < 4; p++) {
            float4 v = aR[p];
            float4 r;
            r.x = fmaxf(fmaf(v.x, sc.x, sh.x), 0.f);
            r.y = fmaxf(fmaf(v.y, sc.y, sh.y), 0.f);
            r.z = fmaxf(fmaf(v.z, sc.z, sh.z), 0.f);
            r.w = fmaxf(fmaf(v.w, sc.w, sh.w), 0.f);
            __half h0 = __float2half_rn(r.x), h1 = __float2half_rn(r.y);
            __half h2 = __float2half_rn(r.z), h3 = __float2half_rn(r.w);
            uint2 hv, lv;
            hv.x = pack_f16(r.x, r.y); hv.y = pack_f16(r.z, r.w);
            lv.x = pack_f16(r.x - __half2float(h0), r.y - __half2float(h1));
            lv.y = pack_f16(r.z - __half2float(h2), r.w - __half2float(h3));
            *reinterpret_cast<uint2*>(dhi + aRow[p] * 144 + aSeg * 8) = hv;
            *reinterpret_cast<uint2*>(dlo + aRow[p] * 144 + aSeg * 8) = lv;
        }
    };

    issueB(0); CP_COMMIT();
    issueB(1); CP_COMMIT();
    loadA(0);

    {
        float* rS = reinterpret_cast<float*>(smem + W2_RED);
        float* rQ = rS + 4 * DD;
        const int col = tid & 127, grp = tid >> 7;
        float s = 0.f, q = 0.f;
        for (int p = grp; p < BN_BLOCKS; p += 4) {
            s += pSin[p * DD + col];
            q += pQin[p * DD + col];
        }
        rS[grp * DD + col] = s;
        rQ[grp * DD + col] = q;
        __syncthreads();
        if (tid < DD) {
            float S = rS[tid] + rS[DD + tid] + rS[2 * DD + tid] + rS[3 * DD + tid];
            float Q = rQ[tid] + rQ[DD + tid] + rQ[2 * DD + tid] + rQ[3 * DD + tid];
            const float inv_m = 1.0f / (float)MTOT;
            float mean = S * inv_m;
            float var  = Q * inv_m - mean * mean;
            float sc   = gamma[tid] * rsqrtf(var + BN_EPS);
            scl[tid] = sc;
            shf[tid] = beta[tid] - mean * sc;
        }
        __syncthreads();
    }

    convertBN(0);
    CP_WAIT1();
    __syncthreads();

    loadA(1);

    {
        const uint32_t stA = sbase;
        const uint32_t stB = sbase + W2_BOFF;
#pragma unroll
        for (int ks = 0; ks < 4; ks++) {
            uint32_t ah[2][4], al[2][4], bh[2][4], bl[2][4];
#pragma unroll
            for (int mb = 0; mb < 2; mb++) {
                uint32_t ad = stA + (rowA + mb * 16) * 144 + (ks * 16 + colA) * 2;
                ldsm_x4(ah[mb], ad);
                ldsm_x4(al[mb], ad + 18432);
            }
#pragma unroll
            for (int g = 0; g < 2; g++) {
                uint32_t bd = stB + (ks * 16 + rowB8) * 272 + (colB + g * 16) * 2;
                ldsm_x4_t(bh[g], bd);
                ldsm_x4_t(bl[g], bd + 17408);
            }
#pragma unroll
            for (int mb = 0; mb < 2; mb++)
#pragma unroll
                for (int nb = 0; nb < 4; nb++)
                    mma_fp16(acc[mb][nb], ah[mb], &bh[nb >> 1][(nb & 1) * 2]);
#pragma unroll
            for (int mb = 0; mb < 2; mb++)
#pragma unroll
                for (int nb = 0; nb < 4; nb++)
                    mma_fp16(acc[mb][nb], ah[mb], &bl[nb >> 1][(nb & 1) * 2]);
#pragma unroll
            for (int mb = 0; mb < 2; mb++)
#pragma unroll
                for (int nb = 0; nb < 4; nb++)
                    mma_fp16(acc[mb][nb], al[mb], &bh[nb >> 1][(nb & 1) * 2]);
        }
    }

    convertBN(1);
    CP_WAIT0();
    __syncthreads();

    {
        const uint32_t stA = sbase + W2_AB;
        const uint32_t stB = sbase + W2_BOFF + W2_BSTG;
#pragma unroll
        for (int ks = 0; ks < 4; ks++) {
            uint32_t ah[2][4], al[2][4], bh[2][4], bl[2][4];
#pragma unroll
            for (int mb = 0; mb < 2; mb++) {
                uint32_t ad = stA + (rowA + mb * 16) * 144 + (ks * 16 + colA) * 2;
                ldsm_x4(ah[mb], ad);
                ldsm_x4(al[mb], ad + 18432);
            }
#pragma unroll
            for (int g = 0; g < 2; g++) {
                uint32_t bd = stB + (ks * 16 + rowB8) * 272 + (colB + g * 16) * 2;
                ldsm_x4_t(bh[g], bd);
                ldsm_x4_t(bl[g], bd + 17408);
            }
#pragma unroll
            for (int mb = 0; mb < 2; mb++)
#pragma unroll
                for (int nb = 0; nb < 4; nb++)
                    mma_fp16(acc[mb][nb], ah[mb], &bh[nb >> 1][(nb & 1) * 2]);
#pragma unroll
            for (int mb = 0; mb < 2; mb++)
#pragma unroll
                for (int nb = 0; nb < 4; nb++)
                    mma_fp16(acc[mb][nb], ah[mb], &bl[nb >> 1][(nb & 1) * 2]);
#pragma unroll
            for (int mb = 0; mb < 2; mb++)
#pragma unroll
                for (int nb = 0; nb < 4; nb++)
                    mma_fp16(acc[mb][nb], al[mb], &bh[nb >> 1][(nb & 1) * 2]);
        }
    }
    __syncthreads();

    const int er = lane >> 2;
    const int ec = (lane & 3) * 2;
    float s8[8], q8[8];
#pragma unroll
    for (int i = 0; i < 8; i++) { s8[i] = 0.f; q8[i] = 0.f; }
#pragma unroll
    for (int mb = 0; mb < 2; mb++)
#pragma unroll
        for (int nb = 0; nb < 4; nb++) {
            int row = wm * 32 + mb * 16 + er;
            int col = wn * 32 + nb * 8 + ec;
            float2 v0 = make_float2(acc[mb][nb][0], acc[mb][nb][1]);
            float2 v1 = make_float2(acc[mb][nb][2], acc[mb][nb][3]);
            float bx = bias[col], by = bias[col + 1];
            v0.x += bx; v0.y += by; v1.x += bx; v1.y += by;
            s8[nb * 2 + 0] += v0.x + v1.x;
            s8[nb * 2 + 1] += v0.y + v1.y;
            q8[nb * 2 + 0] += v0.x * v0.x + v1.x * v1.x;
            q8[nb * 2 + 1] += v0.y * v0.y + v1.y * v1.y;
            *reinterpret_cast<float2*>(outF + aOff + (size_t)row * DD + col) = v0;
            *reinterpret_cast<float2*>(outF + aOff + (size_t)(row + 8) * DD + col) = v1;
        }

#pragma unroll
    for (int off = 4; off < 32; off <<= 1) {
#pragma unroll
        for (int i = 0; i < 8; i++) {
            s8[i] += __shfl_xor_sync(0xFFFFFFFF, s8[i], off);
            q8[i] += __shfl_xor_sync(0xFFFFFFFF, q8[i], off);
        }
    }
    float* sBuf = reinterpret_cast<float*>(smem + W2_RED);
    float* qBuf = sBuf + 4 * DD;
    if (lane < 4) {
#pragma unroll
        for (int nb = 0; nb < 4; nb++) {
#pragma unroll
            for (int j = 0; j < 2; j++) {
                int col = wn * 32 + nb * 8 + lane * 2 + j;
                sBuf[wm * DD + col] = s8[nb * 2 + j];
                qBuf[wm * DD + col] = q8[nb * 2 + j];
            }
        }
    }
    __syncthreads();
    if (tid < DD) {
        float s = sBuf[tid] + sBuf[DD + tid] + sBuf[2 * DD + tid] + sBuf[3 * DD + tid];
        float q = qBuf[tid] + qBuf[DD + tid] + qBuf[2 * DD + tid] + qBuf[3 * DD + tid];
        pSout[blockIdx.x * DD + tid] = s;
        pQout[blockIdx.x * DD + tid] = q;
    }
}

// =================================================================
// Merged preprocessing (verified-correct grid from R15):
// blocks [0,4096): x fp32->fp16 hi; [4096,4128): W1 split;
// [4128,4160): W2 split.
// =================================================================
#define PRE_XBLK 4096
#define PRE_WBLK 32

__global__ __launch_bounds__(256)
void preprocess_kernel(const float* __restrict__ x,
                       const float* __restrict__ W1, const float* __restrict__ W2,
                       __half* __restrict__ hHi,
                       __half* __restrict__ W1Hi, __half* __restrict__ W1Lo,
                       __half* __restrict__ W2Hi, __half* __restrict__ W2Lo) {
    const int b = blockIdx.x;
    if (b < PRE_XBLK) {
        const size_t idx = (size_t)b * 256 + threadIdx.x;
        float4 v = reinterpret_cast<const float4*>(x)[idx];
        uint2 hv;
        hv.x = pack_f16(v.x, v.y); hv.y = pack_f16(v.z, v.w);
        reinterpret_cast<uint2*>(hHi)[idx] = hv;
    } else {
        const bool w2 = (b >= PRE_XBLK + PRE_WBLK);
        const float* src = w2 ? W2 : W1;
        __half* hi = w2 ? W2Hi : W1Hi;
        __half* lo = w2 ? W2Lo : W1Lo;
        const size_t idx = (size_t)(b - (w2 ? PRE_XBLK + PRE_WBLK : PRE_XBLK)) * 256 + threadIdx.x;
        float4 v = reinterpret_cast<const float4*>(src)[idx];
        __half h0 = __float2half_rn(v.x), h1 = __float2half_rn(v.y);
        __half h2 = __float2half_rn(v.z), h3 = __float2half_rn(v.w);
        uint2 hv, lv;
        hv.x = pack_f16(v.x, v.y); hv.y = pack_f16(v.z, v.w);
        lv.x = pack_f16(v.x - __half2float(h0), v.y - __half2float(h1));
        lv.y = pack_f16(v.z - __half2float(h2), v.w - __half2float(h3));
        reinterpret_cast<uint2*>(hi)[idx] = hv;
        reinterpret_cast<uint2*>(lo)[idx] = lv;
    }
}

// =================================================================
// Outer-BN stats+apply (unchanged).
// =================================================================
template <int MODE>
__global__ __launch_bounds__(256)
void bn_stats_apply(const float* __restrict__ gamma, const float* __restrict__ beta,
                    const float* __restrict__ pS, const float* __restrict__ pQ,
                    const float* __restrict__ x,
                    float* __restrict__ outF, __half* __restrict__ yhi) {
    __shared__ float sS[2][DD], sQ[2][DD];
    __shared__ float scl[DD], shf[DD];
    const int tid  = threadIdx.x;
    const int col  = tid & 127;
    const int half = tid >> 7;

    float s = 0.f, q = 0.f;
    for (int p = half; p < BN_BLOCKS; p += 2) {
        s += pS[p * DD + col];
        q += pQ[p * DD + col];
    }
    sS[half][col] = s;
    sQ[half][col] = q;
    __syncthreads();
    if (tid < DD) {
        float S = sS[0][tid] + sS[1][tid];
        float Q = sQ[0][tid] + sQ[1][tid];
        const float inv_m = 1.0f / (float)MTOT;
        float mean = S * inv_m;
        float var  = Q * inv_m - mean * mean;
        float sc   = gamma[tid] * rsqrtf(var + BN_EPS);
        scl[tid] = sc;
        shf[tid] = beta[tid] - mean * sc;
    }
    __syncthreads();

    const int base = blockIdx.x * 8192;
#pragma unroll 8
    for (int i = 0; i < 32; i++) {
        int idx = base + i * 256 + tid;
        int c4  = idx & 31;
        float4 v = reinterpret_cast<const float4*>(x)[idx];
        float4 sc = *reinterpret_cast<const float4*>(&scl[c4 * 4]);
        float4 sh = *reinterpret_cast<const float4*>(&shf[c4 * 4]);
        float4 r;
        r.x = fmaxf(fmaf(v.x, sc.x, sh.x), 0.f);
        r.y = fmaxf(fmaf(v.y, sc.y, sh.y), 0.f);
        r.z = fmaxf(fmaf(v.z, sc.z, sh.z), 0.f);
        r.w = fmaxf(fmaf(v.w, sc.w, sh.w), 0.f);
        if (MODE == 1) {
            reinterpret_cast<float4*>(outF)[idx] = r;
        } else {
            uint2 hv;
            hv.x = pack_f16(r.x, r.y); hv.y = pack_f16(r.z, r.w);
            reinterpret_cast<uint2*>(yhi)[idx] = hv;
        }
    }
}

// ---------------- launch ----------------
extern "C" void kernel_launch(void* const* d_in, const int* in_sizes, int n_in,
                              void* d_out, int out_size) {
    const float* x     = (const float*)d_in[0];
    const float* adj   = (const float*)d_in[2];
    const float* W1    = (const float*)d_in[3];
    const float* b1    = (const float*)d_in[4];
    const float* W2    = (const float*)d_in[5];
    const float* b2    = (const float*)d_in[6];
    const float* g_in   = (const float*)d_in[7];
    const float* be_in  = (const float*)d_in[8];
    const float* g_out  = (const float*)d_in[9];
    const float* be_out = (const float*)d_in[10];
    float* out = (float*)d_out;

    __half *adjH, *hHi, *pHi, *pLo, *W1Hi, *W1Lo, *W2Hi, *W2Lo;
    float *z, *pS1, *pQ1, *pS2, *pQ2;
    cudaGetSymbolAddress((void**)&adjH, g_adjH);
    cudaGetSymbolAddress((void**)&hHi, g_hHi);
    cudaGetSymbolAddress((void**)&pHi, g_pHi);
    cudaGetSymbolAddress((void**)&pLo, g_pLo);
    cudaGetSymbolAddress((void**)&W1Hi, g_W1Hi);
    cudaGetSymbolAddress((void**)&W1Lo, g_W1Lo);
    cudaGetSymbolAddress((void**)&W2Hi, g_W2Hi);
    cudaGetSymbolAddress((void**)&W2Lo, g_W2Lo);
    cudaGetSymbolAddress((void**)&z, g_z);
    cudaGetSymbolAddress((void**)&pS1, g_partS1);
    cudaGetSymbolAddress((void**)&pQ1, g_partQ1);
    cudaGetSymbolAddress((void**)&pS2, g_partS2);
    cudaGetSymbolAddress((void**)&pQ2, g_partQ2);

    constexpr int SMEM3B = 3 * (2 * 128 * 144 + 2 * 64 * 272) + 4096;  // 219136
    constexpr int SMEM1  = 3 * (128 * 144 + 64 * 272);                 // 107520
    cudaFuncSetAttribute((const void*)gemm_pool_convert,
                         cudaFuncAttributeMaxDynamicSharedMemorySize, POOL_SMEM);
    cudaFuncSetAttribute((const void*)gemm_f16<NN, 1, false, 2>,
                         cudaFuncAttributeMaxDynamicSharedMemorySize, SMEM1);
    cudaFuncSetAttribute((const void*)gemm_f16<DD, 3, true, 1>,
                         cudaFuncAttributeMaxDynamicSharedMemorySize, SMEM3B);
    cudaFuncSetAttribute((const void*)gemm_w2_fused,
                         cudaFuncAttributeMaxDynamicSharedMemorySize, W2_SMEM);

    preprocess_kernel<<<PRE_XBLK + 2 * PRE_WBLK, 256>>>(
        x, W1, W2, hHi, W1Hi, W1Lo, W2Hi, W2Lo);

    const dim3 gridPool(NN / 128, BATCH);
    const int  gridW = MTOT / 128;

    for (int l = 0; l < LL; l++) {
        if (l == 0)
            gemm_pool_convert<<<gridPool, 512, POOL_SMEM>>>(
                adj, hHi, adjH, pHi, pLo);
        else
            gemm_f16<NN, 1, false, 2><<<gridPool, 512, SMEM1>>>(
                adjH, nullptr, hHi, nullptr,
                nullptr, nullptr, pHi, pLo, nullptr, nullptr);

        gemm_f16<DD, 3, true, 1><<<gridW, 512, SMEM3B>>>(
            pHi, pLo, W1Hi + (size_t)l * DD * DD, W1Lo + (size_t)l * DD * DD,
            b1 + (size_t)l * DD, z, nullptr, nullptr, pS1, pQ1);

        gemm_w2_fused<<<gridW, 512, W2_SMEM>>>(
            z, W2Hi + (size_t)l * DD * DD, W2Lo + (size_t)l * DD * DD,
            b2 + (size_t)l * DD, g_in + (size_t)l * DD, be_in + (size_t)l * DD,
            pS1, pQ1, z, pS2, pQ2);

        if (l == LL - 1)
            bn_stats_apply<1><<<128, 256>>>(
                g_out + (size_t)l * DD, be_out + (size_t)l * DD, pS2, pQ2,
                z, out, nullptr);
        else
            bn_stats_apply<0><<<128, 256>>>(
                g_out + (size_t)l * DD, be_out + (size_t)l * DD, pS2, pQ2,
                z, nullptr, hHi);
    }
}